// round 4
// baseline (speedup 1.0000x reference)
#include <cuda_runtime.h>

// Problem constants (fixed by the reference)
#define N_ROWS   2000000
#define D        128
#define C        1000
#define DECAY    0.3f

// Tiling: 4 column slices of 32, 37 row chunks -> 148 CTAs (one wave)
#define SLICES      4
#define SLICE_D     32
#define ROW_CHUNKS  37
#define P1_THREADS  1024
#define SUBTILE     8192
#define RPT         (SUBTILE / P1_THREADS)   // rows per thread per subtile = 8

// Shared memory layout (bytes)
#define SM_TABLE      0                      // float[C*SLICE_D]  = 128000
#define SM_CNT        128000                 // int[C]            = 4000
#define SM_START      132000                 // int[C]            = 4000
#define SM_WORK       136000                 // int[C]            = 4000
#define SM_SCAN       140000                 // int[1024]         = 4096
#define SM_CNT_TOT    144096                 // int[C]            = 4000
#define SM_PRES_TOT   148096                 // int[C]            = 4000
#define SM_ORD        152096                 // int[SUBTILE]      = 32768
#define SM_TOTAL      184864

// Global scratch (allocation-free: __device__ arrays)
__device__ float g_sums[C * D];
__device__ float g_counts[C];
__device__ int   g_present[C];

// ---------------------------------------------------------------------------
// Zero the scratch (buffers persist across graph replays)
// ---------------------------------------------------------------------------
__global__ void zero_kernel() {
    int tid    = blockIdx.x * blockDim.x + threadIdx.x;
    int stride = gridDim.x * blockDim.x;
    for (int i = tid; i < C * D; i += stride) g_sums[i] = 0.0f;
    if (tid < C) { g_counts[tid] = 0.0f; g_present[tid] = 0; }
}

// ---------------------------------------------------------------------------
// Accumulate: per (slice, chunk) CTA. Counting-sort each 8192-row subtile by
// class in smem, then one warp per class accumulates its segment in registers
// and does a single non-atomic smem RMW per class. Slice-0 CTAs also produce
// masked counts + presence.
// ---------------------------------------------------------------------------
__global__ void __launch_bounds__(P1_THREADS, 1)
accum_kernel(const float* __restrict__ x,
             const int* __restrict__ y,
             const int* __restrict__ mask) {
    extern __shared__ char sm[];
    float* table    = (float*)(sm + SM_TABLE);
    int*   cnt      = (int*)(sm + SM_CNT);
    int*   start    = (int*)(sm + SM_START);
    int*   work     = (int*)(sm + SM_WORK);
    int*   scanbuf  = (int*)(sm + SM_SCAN);
    int*   cnt_tot  = (int*)(sm + SM_CNT_TOT);
    int*   pres_tot = (int*)(sm + SM_PRES_TOT);
    int*   ord      = (int*)(sm + SM_ORD);

    const int slice = blockIdx.x;
    const int chunk = blockIdx.y;
    const int tid   = threadIdx.x;
    const int warp  = tid >> 5;
    const int lane  = tid & 31;
    const int col   = slice * SLICE_D + lane;

    for (int i = tid; i < C * SLICE_D; i += P1_THREADS) table[i] = 0.0f;
    if (tid < C) { cnt_tot[tid] = 0; pres_tot[tid] = 0; }

    const int rpc  = (N_ROWS + ROW_CHUNKS - 1) / ROW_CHUNKS;
    const int row0 = chunk * rpc;
    const int row1 = (row0 + rpc < N_ROWS) ? (row0 + rpc) : N_ROWS;

    for (int t0 = row0; t0 < row1; t0 += SUBTILE) {
        const int tend = (t0 + SUBTILE < row1) ? (t0 + SUBTILE) : row1;

        // 1) zero per-subtile histogram
        if (tid < C) cnt[tid] = 0;
        __syncthreads();

        // 2) count masked rows per class; keep (class, mask) in registers
        int cls[RPT], msk[RPT];
#pragma unroll
        for (int k = 0; k < RPT; k++) {
            const int r = t0 + tid + k * P1_THREADS;
            cls[k] = -1; msk[k] = 0;
            if (r < tend) {
                cls[k] = y[r];
                msk[k] = mask[r];
                if (slice == 0) atomicAdd(&pres_tot[cls[k]], 1);
                if (msk[k])     atomicAdd(&cnt[cls[k]], 1);
            }
        }
        __syncthreads();

        // 3) exclusive scan over class counts (Hillis-Steele, 1024 lanes)
        scanbuf[tid] = (tid < C) ? cnt[tid] : 0;
        __syncthreads();
        for (int off = 1; off < P1_THREADS; off <<= 1) {
            int v = (tid >= off) ? scanbuf[tid - off] : 0;
            __syncthreads();
            scanbuf[tid] += v;
            __syncthreads();
        }
        if (tid < C) {
            const int s = scanbuf[tid] - cnt[tid];
            start[tid] = s;
            work[tid]  = s;
            if (slice == 0) cnt_tot[tid] += cnt[tid];
        }
        __syncthreads();

        // 4) scatter masked row indices into class-sorted order
#pragma unroll
        for (int k = 0; k < RPT; k++) {
            if (msk[k]) {
                const int p = atomicAdd(&work[cls[k]], 1);
                ord[p] = t0 + tid + k * P1_THREADS;
            }
        }
        __syncthreads();

        // 5) sweep: warp w owns classes w, w+32, ... ; register-accumulate,
        //    one plain smem RMW per class (no races: unique warp per class)
        for (int c = warp; c < C; c += 32) {
            const int s = start[c];
            const int n = cnt[c];
            if (n == 0) continue;
            float acc = 0.0f;
            int i = 0;
            for (; i + 4 <= n; i += 4) {
                const int r0 = ord[s + i];
                const int r1 = ord[s + i + 1];
                const int r2 = ord[s + i + 2];
                const int r3 = ord[s + i + 3];
                const float v0 = x[(long)r0 * D + col];
                const float v1 = x[(long)r1 * D + col];
                const float v2 = x[(long)r2 * D + col];
                const float v3 = x[(long)r3 * D + col];
                acc += (v0 + v1) + (v2 + v3);
            }
            for (; i < n; i++) acc += x[(long)ord[s + i] * D + col];
            table[c * SLICE_D + lane] += acc;
        }
        __syncthreads();
    }

    // Flush slice table into global sums (37 adders per address)
    for (int i = tid; i < C * SLICE_D; i += P1_THREADS) {
        const float v = table[i];
        if (v != 0.0f) {
            const int c = i >> 5;
            const int l = i & 31;
            atomicAdd(&g_sums[c * D + slice * SLICE_D + l], v);
        }
    }
    if (slice == 0 && tid < C) {
        if (pres_tot[tid]) atomicAdd(&g_present[tid], pres_tot[tid]);
        if (cnt_tot[tid])  atomicAdd(&g_counts[tid], (float)cnt_tot[tid]);
    }
}

// ---------------------------------------------------------------------------
// Finalize: avg = sums / max(counts,1); ema; select by presence
// ---------------------------------------------------------------------------
__global__ void finalize_kernel(const float* __restrict__ centroids,
                                float* __restrict__ out) {
    const int c = blockIdx.x;
    const int d = threadIdx.x;
    const float cent = centroids[c * D + d];
    float o = cent;
    if (g_present[c] > 0) {
        const float avg = g_sums[c * D + d] / fmaxf(g_counts[c], 1.0f);
        o = DECAY * avg + (1.0f - DECAY) * cent;
    }
    out[c * D + d] = o;
}

// ---------------------------------------------------------------------------
// Launch
// ---------------------------------------------------------------------------
extern "C" void kernel_launch(void* const* d_in, const int* in_sizes, int n_in,
                              void* d_out, int out_size) {
    const float* x         = (const float*)d_in[0];
    const int*   y         = (const int*)d_in[1];
    const int*   mask      = (const int*)d_in[2];
    const float* centroids = (const float*)d_in[3];
    float*       out       = (float*)d_out;

    (void)in_sizes; (void)n_in; (void)out_size;

    cudaFuncSetAttribute(accum_kernel,
                         cudaFuncAttributeMaxDynamicSharedMemorySize,
                         SM_TOTAL);

    zero_kernel<<<128, 256>>>();
    accum_kernel<<<dim3(SLICES, ROW_CHUNKS), P1_THREADS, SM_TOTAL>>>(x, y, mask);
    finalize_kernel<<<C, D>>>(centroids, out);
}

// round 5
// speedup vs baseline: 1.9072x; 1.9072x over previous
#include <cuda_runtime.h>

// Problem constants (fixed by the reference)
#define N_ROWS   2000000
#define D        128
#define C        1000
#define DECAY    0.3f
#define DUMMY    C               // class slot for masked-out rows (never flushed)

// Tiling: 4 column slices of 32, 37 row chunks -> 148 CTAs (one wave)
#define SLICES      4
#define SLICE_D     32
#define ROW_CHUNKS  37
#define P1_THREADS  1024
#define NWARPS      (P1_THREADS / 32)
#define SUBTILE     12288

#define TSTRIDE     33                         // padded table row stride (floats)
#define TABLE_FLTS  ((C + 1) * TSTRIDE)        // 33033 floats
#define TABLE_BYTES (TABLE_FLTS * 4)           // 132132 B
#define SM_TOTAL    (TABLE_BYTES + SUBTILE * 4)  // + scls = 181284 B

// Global scratch (allocation-free: __device__ arrays)
__device__ float g_sums[C * D];
__device__ float g_counts[C];
__device__ int   g_present[C];

// ---------------------------------------------------------------------------
// Zero the scratch (buffers persist across graph replays)
// ---------------------------------------------------------------------------
__global__ void zero_kernel() {
    int tid    = blockIdx.x * blockDim.x + threadIdx.x;
    int stride = gridDim.x * blockDim.x;
    for (int i = tid; i < C * D; i += stride) g_sums[i] = 0.0f;
    if (tid < C) { g_counts[tid] = 0.0f; g_present[tid] = 0; }
}

// ---------------------------------------------------------------------------
// Counts + presence: one packed int atomic per row.
// low 16 bits: presence count; high 16: masked count (<= 13514 per block, fits)
// ---------------------------------------------------------------------------
__global__ void counts_kernel(const int* __restrict__ y,
                              const int* __restrict__ mask) {
    __shared__ int h[C];
    for (int i = threadIdx.x; i < C; i += blockDim.x) h[i] = 0;
    __syncthreads();

    int stride = gridDim.x * blockDim.x;
    for (int i = blockIdx.x * blockDim.x + threadIdx.x; i < N_ROWS; i += stride) {
        int v = 1 + (mask[i] ? 0x10000 : 0);
        atomicAdd(&h[y[i]], v);
    }
    __syncthreads();

    for (int i = threadIdx.x; i < C; i += blockDim.x) {
        int v = h[i];
        if (v) {
            atomicAdd(&g_present[i], v & 0xFFFF);
            atomicAdd(&g_counts[i], (float)(v >> 16));
        }
    }
}

// ---------------------------------------------------------------------------
// Accumulate. Warp layout: lane = sub*8 + q, sub = row-in-group (0..3),
// q = col-quad (0..7). One LDG.128 warp-op loads 4 rows x 32 cols (512 B).
// scls smem pre-pass folds y+mask into one LDS per group.
// ---------------------------------------------------------------------------
__global__ void __launch_bounds__(P1_THREADS, 1)
accum_kernel(const float* __restrict__ x,
             const int* __restrict__ y,
             const int* __restrict__ mask) {
    extern __shared__ char sm[];
    float* table = (float*)sm;                     // (C+1) x TSTRIDE floats
    int*   scls  = (int*)(sm + TABLE_BYTES);       // SUBTILE ints

    const int slice = blockIdx.x;
    const int chunk = blockIdx.y;
    const int tid   = threadIdx.x;
    const int warp  = tid >> 5;
    const int lane  = tid & 31;
    const int sub   = lane >> 3;        // row within 4-row group
    const int colq  = (lane & 7) * 4;   // col quad within slice

    const float* xs = x + slice * SLICE_D + colq;  // + row*D per access

    for (int i = tid; i < TABLE_FLTS; i += P1_THREADS) table[i] = 0.0f;
    __syncthreads();

    const int rpc  = (N_ROWS + ROW_CHUNKS - 1) / ROW_CHUNKS;
    const int row0 = chunk * rpc;
    const int row1 = (row0 + rpc < N_ROWS) ? (row0 + rpc) : N_ROWS;

    for (int t0 = row0; t0 < row1; t0 += SUBTILE) {
        const int cnt = ((t0 + SUBTILE < row1) ? SUBTILE : (row1 - t0));

        // class pre-pass: fold mask into class id (coalesced LDG + STS)
        for (int i = tid; i < cnt; i += P1_THREADS) {
            const int r = t0 + i;
            scls[i] = mask[r] ? y[r] : DUMMY;
        }
        __syncthreads();

        const int ngroups = cnt >> 2;   // full 4-row groups
        int g = warp;

        // 2x unrolled main loop: 2 LDG.128 + 2 LDS + 8 ATOMS per iteration
        for (; g + NWARPS < ngroups; g += 2 * NWARPS) {
            const int ia = g * 4 + sub;
            const int ib = (g + NWARPS) * 4 + sub;
            const int ca = scls[ia];
            const int cb = scls[ib];
            const float4 va = *(const float4*)(xs + (long)(t0 + ia) * D);
            const float4 vb = *(const float4*)(xs + (long)(t0 + ib) * D);
            float* ta = &table[ca * TSTRIDE + colq];
            float* tb = &table[cb * TSTRIDE + colq];
            atomicAdd(ta + 0, va.x); atomicAdd(ta + 1, va.y);
            atomicAdd(ta + 2, va.z); atomicAdd(ta + 3, va.w);
            atomicAdd(tb + 0, vb.x); atomicAdd(tb + 1, vb.y);
            atomicAdd(tb + 2, vb.z); atomicAdd(tb + 3, vb.w);
        }
        for (; g < ngroups; g += NWARPS) {
            const int ia = g * 4 + sub;
            const int ca = scls[ia];
            const float4 va = *(const float4*)(xs + (long)(t0 + ia) * D);
            float* ta = &table[ca * TSTRIDE + colq];
            atomicAdd(ta + 0, va.x); atomicAdd(ta + 1, va.y);
            atomicAdd(ta + 2, va.z); atomicAdd(ta + 3, va.w);
        }

        // tail rows (cnt & 3), warp 0 only, per-lane guard
        const int tail0 = ngroups * 4;
        if (warp == 0 && tail0 < cnt) {
            const int i = tail0 + sub;
            if (i < cnt) {
                const int ca = scls[i];
                const float4 va = *(const float4*)(xs + (long)(t0 + i) * D);
                float* ta = &table[ca * TSTRIDE + colq];
                atomicAdd(ta + 0, va.x); atomicAdd(ta + 1, va.y);
                atomicAdd(ta + 2, va.z); atomicAdd(ta + 3, va.w);
            }
        }
        __syncthreads();
    }

    // flush slice table into global sums (37 adders per address)
    for (int i = tid; i < C * SLICE_D; i += P1_THREADS) {
        const int c   = i >> 5;
        const int col = i & 31;
        const float v = table[c * TSTRIDE + col];
        if (v != 0.0f) atomicAdd(&g_sums[c * D + slice * SLICE_D + col], v);
    }
}

// ---------------------------------------------------------------------------
// Finalize: avg = sums / max(counts,1); ema; select by presence
// ---------------------------------------------------------------------------
__global__ void finalize_kernel(const float* __restrict__ centroids,
                                float* __restrict__ out) {
    const int c = blockIdx.x;
    const int d = threadIdx.x;
    const float cent = centroids[c * D + d];
    float o = cent;
    if (g_present[c] > 0) {
        const float avg = g_sums[c * D + d] / fmaxf(g_counts[c], 1.0f);
        o = DECAY * avg + (1.0f - DECAY) * cent;
    }
    out[c * D + d] = o;
}

// ---------------------------------------------------------------------------
// Launch
// ---------------------------------------------------------------------------
extern "C" void kernel_launch(void* const* d_in, const int* in_sizes, int n_in,
                              void* d_out, int out_size) {
    const float* x         = (const float*)d_in[0];
    const int*   y         = (const int*)d_in[1];
    const int*   mask      = (const int*)d_in[2];
    const float* centroids = (const float*)d_in[3];
    float*       out       = (float*)d_out;

    (void)in_sizes; (void)n_in; (void)out_size;

    cudaFuncSetAttribute(accum_kernel,
                         cudaFuncAttributeMaxDynamicSharedMemorySize,
                         SM_TOTAL);

    zero_kernel<<<128, 256>>>();
    counts_kernel<<<148, 1024>>>(y, mask);
    accum_kernel<<<dim3(SLICES, ROW_CHUNKS), P1_THREADS, SM_TOTAL>>>(x, y, mask);
    finalize_kernel<<<C, D>>>(centroids, out);
}

// round 6
// speedup vs baseline: 2.6146x; 1.3709x over previous
#include <cuda_runtime.h>

// Problem constants (fixed by the reference)
#define N_ROWS   2000000
#define D        128
#define C        1000
#define DECAY    0.3f

// Histogram/scatter decomposition
#define HB        148
#define RB        ((N_ROWS + HB - 1) / HB)      // 13514 rows per block

// Gather-accumulate decomposition
#define A_CTAS     296
#define A_THREADS  512
#define A_WARPS    (A_CTAS * (A_THREADS / 32))  // 4736 warps
#define WSPAN      ((N_ROWS + A_WARPS - 1) / A_WARPS)  // 423 positions per warp

// Global scratch (allocation-free: __device__ arrays)
__device__ float g_sums[C * D];
__device__ float g_counts[C];
__device__ int   g_present[C];
__device__ int   g_bh[HB * C];      // per-block masked-class histogram -> col prefix
__device__ int   g_base[C];         // global class base offsets
__device__ int   g_M;               // total masked rows
__device__ int2  g_pair[N_ROWS];    // class-sorted (row, class)

// ---------------------------------------------------------------------------
__global__ void zero_kernel() {
    int tid    = blockIdx.x * blockDim.x + threadIdx.x;
    int stride = gridDim.x * blockDim.x;
    for (int i = tid; i < C * D; i += stride) g_sums[i] = 0.0f;
    if (tid < C) { g_counts[tid] = 0.0f; g_present[tid] = 0; }
}

// ---------------------------------------------------------------------------
// Per-block class histogram (packed: low16 presence of all rows, high16 masked),
// plus global presence/counts accumulation.
// ---------------------------------------------------------------------------
__global__ void hist_kernel(const int* __restrict__ y,
                            const int* __restrict__ mask) {
    __shared__ int h[C];
    for (int i = threadIdx.x; i < C; i += blockDim.x) h[i] = 0;
    __syncthreads();

    const int r0 = blockIdx.x * RB;
    const int r1 = (r0 + RB < N_ROWS) ? (r0 + RB) : N_ROWS;
    for (int i = r0 + threadIdx.x; i < r1; i += blockDim.x) {
        const int m = mask[i] ? 1 : 0;
        atomicAdd(&h[y[i]], 1 + (m << 16));
    }
    __syncthreads();

    for (int i = threadIdx.x; i < C; i += blockDim.x) {
        const int v = h[i];
        g_bh[blockIdx.x * C + i] = v >> 16;   // masked count for the sort
        if (v) {
            atomicAdd(&g_present[i], v & 0xFFFF);
            if (v >> 16) atomicAdd(&g_counts[i], (float)(v >> 16));
        }
    }
}

// ---------------------------------------------------------------------------
// One-block scan: per-class column prefix over blocks (in place in g_bh),
// then exclusive scan of class totals -> g_base, g_M.
// ---------------------------------------------------------------------------
__global__ void scan_kernel() {
    __shared__ int sb[1024];
    const int tid = threadIdx.x;

    int t = 0;
    if (tid < C) {
        int run = 0;
        for (int b = 0; b < HB; b++) {
            const int hv = g_bh[b * C + tid];
            g_bh[b * C + tid] = run;       // exclusive per-class block prefix
            run += hv;
        }
        t = run;
    }
    sb[tid] = t;
    __syncthreads();
    for (int off = 1; off < 1024; off <<= 1) {
        const int v = (tid >= off) ? sb[tid - off] : 0;
        __syncthreads();
        sb[tid] += v;
        __syncthreads();
    }
    if (tid < C)     g_base[tid] = sb[tid] - t;  // exclusive base
    if (tid == C - 1) g_M = sb[tid];             // total masked rows
}

// ---------------------------------------------------------------------------
// Scatter (row, class) pairs into class-sorted order.
// ---------------------------------------------------------------------------
__global__ void scatter_kernel(const int* __restrict__ y,
                               const int* __restrict__ mask) {
    __shared__ int cur[C];
    const int b = blockIdx.x;
    for (int i = threadIdx.x; i < C; i += blockDim.x)
        cur[i] = g_base[i] + g_bh[b * C + i];
    __syncthreads();

    const int r0 = b * RB;
    const int r1 = (r0 + RB < N_ROWS) ? (r0 + RB) : N_ROWS;
    for (int i = r0 + threadIdx.x; i < r1; i += blockDim.x) {
        if (mask[i]) {
            const int c = y[i];
            const int p = atomicAdd(&cur[c], 1);
            g_pair[p] = make_int2(i, c);
        }
    }
}

// ---------------------------------------------------------------------------
// Gather-accumulate over the class-sorted order. One warp owns a contiguous
// span of sorted positions; class is warp-uniform; runs accumulate in
// registers (float4 per lane = 128 cols per warp); flush to g_sums with a
// handful of global atomics per class transition.
// ---------------------------------------------------------------------------
__global__ void __launch_bounds__(A_THREADS, 2)
accum2_kernel(const float* __restrict__ x) {
    const int lane = threadIdx.x & 31;
    const int warp = threadIdx.x >> 5;
    const int W    = blockIdx.x * (A_THREADS / 32) + warp;

    const int M     = g_M;
    const int start = W * WSPAN;
    int end = start + WSPAN;
    if (end > M) end = M;
    const int n = end - start;
    if (n <= 0) return;

    const float* xc = x + lane * 4;
    float4 acc = make_float4(0.f, 0.f, 0.f, 0.f);
    int cur = -1;

    int2 pr[4];
#pragma unroll
    for (int k = 0; k < 4; k++)
        pr[k] = (k < n) ? g_pair[start + k] : make_int2(0, -1);

    int i = 0;
    while (i < n) {
        // load x rows for current chunk
        float4 v[4];
#pragma unroll
        for (int k = 0; k < 4; k++) {
            if (pr[k].y >= 0)
                v[k] = *(const float4*)(xc + (long)pr[k].x * D);
            else
                v[k] = make_float4(0.f, 0.f, 0.f, 0.f);
        }
        // prefetch next chunk's pairs
        const int j = i + 4;
        int2 np[4];
#pragma unroll
        for (int k = 0; k < 4; k++)
            np[k] = (j + k < n) ? g_pair[start + j + k] : make_int2(0, -1);

        // process current chunk (class is warp-uniform -> uniform branches)
#pragma unroll
        for (int k = 0; k < 4; k++) {
            const int c = pr[k].y;
            if (c != cur) {
                if (cur >= 0) {
                    float* t = &g_sums[cur * D + lane * 4];
                    atomicAdd(t + 0, acc.x); atomicAdd(t + 1, acc.y);
                    atomicAdd(t + 2, acc.z); atomicAdd(t + 3, acc.w);
                }
                cur = c;
                acc = make_float4(0.f, 0.f, 0.f, 0.f);
            }
            if (c >= 0) {
                acc.x += v[k].x; acc.y += v[k].y;
                acc.z += v[k].z; acc.w += v[k].w;
            }
        }
#pragma unroll
        for (int k = 0; k < 4; k++) pr[k] = np[k];
        i = j;
    }
    if (cur >= 0) {
        float* t = &g_sums[cur * D + lane * 4];
        atomicAdd(t + 0, acc.x); atomicAdd(t + 1, acc.y);
        atomicAdd(t + 2, acc.z); atomicAdd(t + 3, acc.w);
    }
}

// ---------------------------------------------------------------------------
// Finalize: avg = sums / max(counts,1); ema; select by presence
// ---------------------------------------------------------------------------
__global__ void finalize_kernel(const float* __restrict__ centroids,
                                float* __restrict__ out) {
    const int c = blockIdx.x;
    const int d = threadIdx.x;
    const float cent = centroids[c * D + d];
    float o = cent;
    if (g_present[c] > 0) {
        const float avg = g_sums[c * D + d] / fmaxf(g_counts[c], 1.0f);
        o = DECAY * avg + (1.0f - DECAY) * cent;
    }
    out[c * D + d] = o;
}

// ---------------------------------------------------------------------------
// Launch
// ---------------------------------------------------------------------------
extern "C" void kernel_launch(void* const* d_in, const int* in_sizes, int n_in,
                              void* d_out, int out_size) {
    const float* x         = (const float*)d_in[0];
    const int*   y         = (const int*)d_in[1];
    const int*   mask      = (const int*)d_in[2];
    const float* centroids = (const float*)d_in[3];
    float*       out       = (float*)d_out;

    (void)in_sizes; (void)n_in; (void)out_size;

    zero_kernel<<<128, 256>>>();
    hist_kernel<<<HB, 1024>>>(y, mask);
    scan_kernel<<<1, 1024>>>();
    scatter_kernel<<<HB, 1024>>>(y, mask);
    accum2_kernel<<<A_CTAS, A_THREADS>>>(x);
    finalize_kernel<<<C, D>>>(centroids, out);
}

// round 8
// speedup vs baseline: 2.6596x; 1.0172x over previous
#include <cuda_runtime.h>

// Problem constants (fixed by the reference)
#define N_ROWS   2000000
#define D        128
#define C        1000
#define DECAY    0.3f

// Histogram/scatter decomposition
#define HB        148
#define RB        ((N_ROWS + HB - 1) / HB)      // 13514 rows per block

// Gather-accumulate decomposition
#define A_CTAS     296
#define A_THREADS  512
#define A_WARPS    (A_CTAS * (A_THREADS / 32))  // 4736 warps
#define WSPAN      ((N_ROWS + A_WARPS - 1) / A_WARPS)  // 423 positions per warp

// Packed pair: p = (class << 21) | row   (row < 2^21, class < 2^10)
#define ROW_BITS   21
#define ROW_MASK   ((1 << ROW_BITS) - 1)

// Global scratch (allocation-free: __device__ arrays)
__device__ float g_sums[C * D];
__device__ float g_counts[C];
__device__ int   g_present[C];
__device__ int   g_bh[HB * C];      // per-block masked histogram -> block prefix
__device__ int   g_ctot[C];         // per-class masked totals
__device__ int   g_base[C];         // global class base offsets
__device__ int   g_M;               // total masked rows
__device__ int   g_pair[N_ROWS];    // class-sorted packed (class,row)

// ---------------------------------------------------------------------------
__global__ void zero_kernel() {
    int tid    = blockIdx.x * blockDim.x + threadIdx.x;
    int stride = gridDim.x * blockDim.x;
    for (int i = tid; i < C * D; i += stride) g_sums[i] = 0.0f;
    if (tid < C) { g_counts[tid] = 0.0f; g_present[tid] = 0; }
}

// ---------------------------------------------------------------------------
// Per-block class histogram (packed: low16 presence, high16 masked),
// plus global presence/counts accumulation.
// ---------------------------------------------------------------------------
__global__ void hist_kernel(const int* __restrict__ y,
                            const int* __restrict__ mask) {
    __shared__ int h[C];
    for (int i = threadIdx.x; i < C; i += blockDim.x) h[i] = 0;
    __syncthreads();

    const int r0 = blockIdx.x * RB;
    const int r1 = (r0 + RB < N_ROWS) ? (r0 + RB) : N_ROWS;
    for (int i = r0 + threadIdx.x; i < r1; i += blockDim.x) {
        const int m = mask[i] ? 1 : 0;
        atomicAdd(&h[y[i]], 1 + (m << 16));
    }
    __syncthreads();

    for (int i = threadIdx.x; i < C; i += blockDim.x) {
        const int v = h[i];
        g_bh[blockIdx.x * C + i] = v >> 16;   // masked count for the sort
        if (v) {
            atomicAdd(&g_present[i], v & 0xFFFF);
            if (v >> 16) atomicAdd(&g_counts[i], (float)(v >> 16));
        }
    }
}

// ---------------------------------------------------------------------------
// Scan stage 1: per-class exclusive prefix across the 148 block histograms
// (one thread per class, 8 CTAs -> coalesced column walks on 8 SMs).
// ---------------------------------------------------------------------------
__global__ void scan1_kernel() {
    const int c = blockIdx.x * blockDim.x + threadIdx.x;
    if (c >= C) return;
    int run = 0;
    for (int b = 0; b < HB; b++) {
        const int hv = g_bh[b * C + c];
        g_bh[b * C + c] = run;
        run += hv;
    }
    g_ctot[c] = run;
}

// ---------------------------------------------------------------------------
// Scan stage 2: exclusive scan of the 1000 class totals (one block).
// ---------------------------------------------------------------------------
__global__ void scan2_kernel() {
    __shared__ int sb[1024];
    const int tid = threadIdx.x;
    const int t = (tid < C) ? g_ctot[tid] : 0;
    sb[tid] = t;
    __syncthreads();
    for (int off = 1; off < 1024; off <<= 1) {
        const int v = (tid >= off) ? sb[tid - off] : 0;
        __syncthreads();
        sb[tid] += v;
        __syncthreads();
    }
    if (tid < C)      g_base[tid] = sb[tid] - t;   // exclusive base
    if (tid == C - 1) g_M = sb[tid];               // total masked rows
}

// ---------------------------------------------------------------------------
// Scatter packed (class,row) into class-sorted order (4B random writes).
// ---------------------------------------------------------------------------
__global__ void scatter_kernel(const int* __restrict__ y,
                               const int* __restrict__ mask) {
    __shared__ int cur[C];
    const int b = blockIdx.x;
    for (int i = threadIdx.x; i < C; i += blockDim.x)
        cur[i] = g_base[i] + g_bh[b * C + i];
    __syncthreads();

    const int r0 = b * RB;
    const int r1 = (r0 + RB < N_ROWS) ? (r0 + RB) : N_ROWS;
    for (int i = r0 + threadIdx.x; i < r1; i += blockDim.x) {
        if (mask[i]) {
            const int c = y[i];
            const int p = atomicAdd(&cur[c], 1);
            g_pair[p] = (c << ROW_BITS) | i;
        }
    }
}

// ---------------------------------------------------------------------------
// Gather-accumulate over class-sorted order. One warp owns a contiguous span;
// class is warp-uniform; runs accumulate in registers (float4/lane = 128 cols
// per warp); a handful of global atomics at class transitions.
// ---------------------------------------------------------------------------
__global__ void __launch_bounds__(A_THREADS, 2)
accum2_kernel(const float* __restrict__ x) {
    const int lane = threadIdx.x & 31;
    const int warp = threadIdx.x >> 5;
    const int W    = blockIdx.x * (A_THREADS / 32) + warp;

    const int M     = g_M;
    const int start = W * WSPAN;
    int end = start + WSPAN;
    if (end > M) end = M;
    const int n = end - start;
    if (n <= 0) return;

    const float* xc = x + lane * 4;
    float4 acc = make_float4(0.f, 0.f, 0.f, 0.f);
    int cur = -1;

    int pr[4];
#pragma unroll
    for (int k = 0; k < 4; k++)
        pr[k] = (k < n) ? g_pair[start + k] : -1;

    int i = 0;
    while (i < n) {
        // load x rows for current chunk
        float4 v[4];
#pragma unroll
        for (int k = 0; k < 4; k++) {
            if (pr[k] >= 0)
                v[k] = *(const float4*)(xc + (long)(pr[k] & ROW_MASK) * D);
            else
                v[k] = make_float4(0.f, 0.f, 0.f, 0.f);
        }
        // prefetch next chunk's pairs
        const int j = i + 4;
        int np[4];
#pragma unroll
        for (int k = 0; k < 4; k++)
            np[k] = (j + k < n) ? g_pair[start + j + k] : -1;

        // process current chunk (class is warp-uniform -> uniform branches)
#pragma unroll
        for (int k = 0; k < 4; k++) {
            const int c = (pr[k] >= 0) ? (pr[k] >> ROW_BITS) : -1;
            if (c != cur) {
                if (cur >= 0) {
                    float* t = &g_sums[cur * D + lane * 4];
                    atomicAdd(t + 0, acc.x); atomicAdd(t + 1, acc.y);
                    atomicAdd(t + 2, acc.z); atomicAdd(t + 3, acc.w);
                }
                cur = c;
                acc = make_float4(0.f, 0.f, 0.f, 0.f);
            }
            if (c >= 0) {
                acc.x += v[k].x; acc.y += v[k].y;
                acc.z += v[k].z; acc.w += v[k].w;
            }
        }
#pragma unroll
        for (int k = 0; k < 4; k++) pr[k] = np[k];
        i = j;
    }
    if (cur >= 0) {
        float* t = &g_sums[cur * D + lane * 4];
        atomicAdd(t + 0, acc.x); atomicAdd(t + 1, acc.y);
        atomicAdd(t + 2, acc.z); atomicAdd(t + 3, acc.w);
    }
}

// ---------------------------------------------------------------------------
// Finalize: avg = sums / max(counts,1); ema; select by presence
// ---------------------------------------------------------------------------
__global__ void finalize_kernel(const float* __restrict__ centroids,
                                float* __restrict__ out) {
    const int c = blockIdx.x;
    const int d = threadIdx.x;
    const float cent = centroids[c * D + d];
    float o = cent;
    if (g_present[c] > 0) {
        const float avg = g_sums[c * D + d] / fmaxf(g_counts[c], 1.0f);
        o = DECAY * avg + (1.0f - DECAY) * cent;
    }
    out[c * D + d] = o;
}

// ---------------------------------------------------------------------------
// Launch
// ---------------------------------------------------------------------------
extern "C" void kernel_launch(void* const* d_in, const int* in_sizes, int n_in,
                              void* d_out, int out_size) {
    const float* x         = (const float*)d_in[0];
    const int*   y         = (const int*)d_in[1];
    const int*   mask      = (const int*)d_in[2];
    const float* centroids = (const float*)d_in[3];
    float*       out       = (float*)d_out;

    (void)in_sizes; (void)n_in; (void)out_size;

    zero_kernel<<<128, 256>>>();
    hist_kernel<<<HB, 1024>>>(y, mask);
    scan1_kernel<<<(C + 127) / 128, 128>>>();
    scan2_kernel<<<1, 1024>>>();
    scatter_kernel<<<HB, 1024>>>(y, mask);
    accum2_kernel<<<A_CTAS, A_THREADS>>>(x);
    finalize_kernel<<<C, D>>>(centroids, out);
}